// round 2
// baseline (speedup 1.0000x reference)
#include <cuda_runtime.h>
#include <math.h>

#define DIM 1024
#define DI  1024
#define BAT 8
#define TT  2048
#define MM  (BAT*TT)   /* 16384 rows */
#define EPS 1e-6f

// Scratch (device globals: allocation-free per harness rules)
__device__ float g_xp[(size_t)MM * DI];    // silu(x @ W_in^T)
__device__ float g_wx[(size_t)MM * DI];    // xp @ W_cell^T + b
__device__ float g_gate[(size_t)MM * DI];  // scan output (pre out_proj)

__device__ __forceinline__ float silu_f(float v) {
    return v * (1.0f / (1.0f + __expf(-v)));
}

// ---------------------------------------------------------------------------
// GEMM: C[M,N] = A[M,K] * W[N,K]^T  (NT, both K-contiguous)
// 128x128 tile, BK=16, 256 threads, 8x8 per thread, fp32.
// EPI : 0 = none, 1 = silu, 2 = +bias
// ASRC: 0 = external A, 1 = g_xp, 2 = g_gate
// DST : 0 = g_xp, 1 = g_wx, 2 = external C
// ---------------------------------------------------------------------------
template<int EPI, int ASRC, int DST>
__global__ __launch_bounds__(256)
void gemm_nt(const float* __restrict__ Aext, const float* __restrict__ W,
             const float* __restrict__ bias, float* __restrict__ Cout,
             int N, int K)
{
    __shared__ float As[16][132];   // [k][m], padded
    __shared__ float Bs[16][132];   // [k][n]

    const float* A = (ASRC == 0) ? Aext : (ASRC == 1) ? g_xp : g_gate;
    float*       C = (DST  == 0) ? g_xp : (DST  == 1) ? g_wx : Cout;

    const int tid  = threadIdx.x;
    const int brow = blockIdx.y * 128;
    const int bcol = blockIdx.x * 128;
    const int ty = tid >> 4;      // 0..15
    const int tx = tid & 15;      // 0..15

    float acc[8][8];
    #pragma unroll
    for (int i = 0; i < 8; i++)
        #pragma unroll
        for (int j = 0; j < 8; j++) acc[i][j] = 0.f;

    for (int k0 = 0; k0 < K; k0 += 16) {
        #pragma unroll
        for (int i = 0; i < 2; i++) {
            int idx = tid + i * 256;      // 0..511
            int r   = idx >> 2;           // 0..127
            int c4  = idx & 3;            // 0..3
            float4 va = *(const float4*)&A[(size_t)(brow + r) * K + k0 + c4 * 4];
            As[c4*4+0][r] = va.x; As[c4*4+1][r] = va.y;
            As[c4*4+2][r] = va.z; As[c4*4+3][r] = va.w;
            float4 vb = *(const float4*)&W[(size_t)(bcol + r) * K + k0 + c4 * 4];
            Bs[c4*4+0][r] = vb.x; Bs[c4*4+1][r] = vb.y;
            Bs[c4*4+2][r] = vb.z; Bs[c4*4+3][r] = vb.w;
        }
        __syncthreads();

        #pragma unroll
        for (int k = 0; k < 16; k++) {
            float a[8], b[8];
            *(float4*)(a)     = *(const float4*)&As[k][ty*8];
            *(float4*)(a + 4) = *(const float4*)&As[k][ty*8 + 4];
            *(float4*)(b)     = *(const float4*)&Bs[k][tx*8];
            *(float4*)(b + 4) = *(const float4*)&Bs[k][tx*8 + 4];
            #pragma unroll
            for (int i = 0; i < 8; i++)
                #pragma unroll
                for (int j = 0; j < 8; j++)
                    acc[i][j] = fmaf(a[i], b[j], acc[i][j]);
        }
        __syncthreads();
    }

    #pragma unroll
    for (int i = 0; i < 8; i++) {
        int row = brow + ty * 8 + i;
        #pragma unroll
        for (int j0 = 0; j0 < 8; j0 += 4) {
            int col = bcol + tx * 8 + j0;
            float e0 = acc[i][j0+0], e1 = acc[i][j0+1];
            float e2 = acc[i][j0+2], e3 = acc[i][j0+3];
            if (EPI == 1) {
                e0 = silu_f(e0); e1 = silu_f(e1); e2 = silu_f(e2); e3 = silu_f(e3);
            } else if (EPI == 2) {
                e0 += bias[col+0]; e1 += bias[col+1];
                e2 += bias[col+2]; e3 += bias[col+3];
            }
            float4 v; v.x = e0; v.y = e1; v.z = e2; v.w = e3;
            *(float4*)&C[(size_t)row * N + col] = v;
        }
    }
}

// ---------------------------------------------------------------------------
// Sequential scan over T: h += alpha*wx; RMSNorm; out = h*silu(h)
// 1 block / batch, 1024 threads (1 channel each), h in registers,
// wx prefetched one step ahead.
// ---------------------------------------------------------------------------
__global__ __launch_bounds__(1024)
void scan_kernel(const float* __restrict__ h0,
                 const float* __restrict__ log_alpha,
                 float* __restrict__ h_final)
{
    const int b   = blockIdx.x;
    const int tid = threadIdx.x;
    __shared__ float warp_s[32];
    __shared__ float s_r;

    const float alpha = expf(log_alpha[0]);
    float h = h0[b * DI + tid];

    const size_t base = (size_t)b * TT * DI + tid;
    float wx = g_wx[base];

    for (int t = 0; t < TT; t++) {
        float wx_next = (t + 1 < TT) ? g_wx[base + (size_t)(t + 1) * DI] : 0.f;

        h = fmaf(alpha, wx, h);

        // block-wide sum of h^2
        float s = h * h;
        #pragma unroll
        for (int o = 16; o; o >>= 1) s += __shfl_xor_sync(0xffffffffu, s, o);
        if ((tid & 31) == 0) warp_s[tid >> 5] = s;
        __syncthreads();
        if (tid < 32) {
            float v = warp_s[tid];
            #pragma unroll
            for (int o = 16; o; o >>= 1) v += __shfl_xor_sync(0xffffffffu, v, o);
            if (tid == 0) s_r = rsqrtf(v * (1.0f / DI) + EPS);
        }
        __syncthreads();

        h *= s_r;
        float sg = 1.0f / (1.0f + __expf(-h));
        g_gate[base + (size_t)t * DI] = h * h * sg;   // h * silu(h)

        wx = wx_next;
    }

    if (h_final) h_final[b * DI + tid] = h;
}

// ---------------------------------------------------------------------------
extern "C" void kernel_launch(void* const* d_in, const int* in_sizes, int n_in,
                              void* d_out, int out_size)
{
    const float* x         = (const float*)d_in[0];
    const float* h0        = (const float*)d_in[1];
    const float* W_in      = (const float*)d_in[2];
    const float* W_cell    = (const float*)d_in[3];
    const float* b_cell    = (const float*)d_in[4];
    const float* log_alpha = (const float*)d_in[5];
    const float* W_out     = (const float*)d_in[6];

    float* y = (float*)d_out;
    const size_t y_elems = (size_t)MM * DIM;
    float* h_final = ((size_t)out_size >= y_elems + (size_t)BAT * DI)
                         ? y + y_elems : nullptr;

    dim3 block(256);
    dim3 grid(DI / 128, MM / 128);

    // 1) xp = silu(x @ W_in^T)          -> g_xp
    gemm_nt<1, 0, 0><<<grid, block>>>(x, W_in, nullptr, nullptr, DI, DIM);
    // 2) Wx = xp @ W_cell^T + b_cell    -> g_wx
    gemm_nt<2, 1, 1><<<grid, block>>>(nullptr, W_cell, b_cell, nullptr, DI, DI);
    // 3) scan                            -> g_gate, h_final
    scan_kernel<<<BAT, 1024>>>(h0, log_alpha, h_final);
    // 4) y = gate @ W_out^T             -> d_out
    gemm_nt<0, 2, 2><<<dim3(DIM / 128, MM / 128), block>>>(nullptr, W_out, nullptr, y, DIM, DI);
}

// round 3
// speedup vs baseline: 1.2985x; 1.2985x over previous
#include <cuda_runtime.h>
#include <math.h>
#include <stdint.h>

#define DIM 1024
#define DI  1024
#define BAT 8
#define TT  2048
#define MM  (BAT*TT)   /* 16384 rows */
#define EPS 1e-6f

// Scratch (device globals: allocation-free per harness rules)
__device__ float g_xp[(size_t)MM * DI];    // silu(x @ W_in^T)
__device__ float g_wx[(size_t)MM * DI];    // xp @ W_cell^T + b
__device__ float g_gate[(size_t)MM * DI];  // scan output (pre out_proj)

__device__ __forceinline__ float silu_f(float v) {
    return v * (1.0f / (1.0f + __expf(-v)));
}

__device__ __forceinline__ uint32_t f2tf32(float f) {
    uint32_t u;
    asm("cvt.rna.tf32.f32 %0, %1;" : "=r"(u) : "f"(f));
    return u;
}

// ---------------------------------------------------------------------------
// TF32 tensor-core GEMM: C[M,N] = A[M,K] * W[N,K]^T  (NT, K-contiguous)
// Block tile 128x128x32, 256 threads = 8 warps (2 M x 4 N), warp tile 64x32.
// mma.sync.m16n8k8.tf32. Register-staged double buffer on the K loop.
// EPI : 0 = none, 1 = silu, 2 = +bias
// ASRC: 0 = external A, 1 = g_xp, 2 = g_gate
// DST : 0 = g_xp, 1 = g_wx, 2 = external C
// ---------------------------------------------------------------------------
#define PAD 36   // smem row pitch (floats): frag-LDS banks = 4*g + tg, conflict-free

template<int EPI, int ASRC, int DST>
__global__ __launch_bounds__(256)
void gemm_tf32(const float* __restrict__ Aext, const float* __restrict__ W,
               const float* __restrict__ bias, float* __restrict__ Cout,
               int N, int K)
{
    __shared__ uint32_t As[128][PAD];
    __shared__ uint32_t Bs[128][PAD];

    const float* A = (ASRC == 0) ? Aext : (ASRC == 1) ? g_xp : g_gate;
    float*       C = (DST  == 0) ? g_xp : (DST  == 1) ? g_wx : Cout;

    const int tid  = threadIdx.x;
    const int brow = blockIdx.y * 128;
    const int bcol = blockIdx.x * 128;

    const int warp = tid >> 5;
    const int lane = tid & 31;
    const int g    = lane >> 2;   // 0..7
    const int tg   = lane & 3;    // 0..3
    const int warp_m = (warp & 1) * 64;   // 2 warps along M
    const int warp_n = (warp >> 1) * 32;  // 4 warps along N

    // staging: each thread loads one half-row (16 floats) of A and of B per chunk
    const int rA   = tid >> 1;          // 0..127
    const int colA = (tid & 1) * 16;    // 0 or 16
    const float* aptr = A + (size_t)(brow + rA) * K + colA;
    const float* bptr = W + (size_t)(bcol + rA) * K + colA;

    float4 sa[4], sb[4];

    // prologue: stage chunk 0
    #pragma unroll
    for (int i = 0; i < 4; i++) {
        sa[i] = *(const float4*)(aptr + i * 4);
        sb[i] = *(const float4*)(bptr + i * 4);
    }

    float acc[4][4][4];
    #pragma unroll
    for (int i = 0; i < 4; i++)
        #pragma unroll
        for (int j = 0; j < 4; j++)
            #pragma unroll
            for (int r = 0; r < 4; r++) acc[i][j][r] = 0.f;

    const int nchunks = K >> 5;   // K/32
    for (int ch = 0; ch < nchunks; ch++) {
        __syncthreads();   // previous compute done before smem overwrite
        #pragma unroll
        for (int i = 0; i < 4; i++) {
            As[rA][colA + i*4 + 0] = f2tf32(sa[i].x);
            As[rA][colA + i*4 + 1] = f2tf32(sa[i].y);
            As[rA][colA + i*4 + 2] = f2tf32(sa[i].z);
            As[rA][colA + i*4 + 3] = f2tf32(sa[i].w);
            Bs[rA][colA + i*4 + 0] = f2tf32(sb[i].x);
            Bs[rA][colA + i*4 + 1] = f2tf32(sb[i].y);
            Bs[rA][colA + i*4 + 2] = f2tf32(sb[i].z);
            Bs[rA][colA + i*4 + 3] = f2tf32(sb[i].w);
        }
        __syncthreads();

        // stage next chunk (overlaps DRAM latency with compute below)
        if (ch + 1 < nchunks) {
            const float* ap = aptr + (ch + 1) * 32;
            const float* bp = bptr + (ch + 1) * 32;
            #pragma unroll
            for (int i = 0; i < 4; i++) {
                sa[i] = *(const float4*)(ap + i * 4);
                sb[i] = *(const float4*)(bp + i * 4);
            }
        }

        // compute: 4 k8 steps, 16 mma each
        #pragma unroll
        for (int ks = 0; ks < 4; ks++) {
            const int kk = ks * 8;
            uint32_t af[4][4], bf[4][2];
            #pragma unroll
            for (int i = 0; i < 4; i++) {
                int r0 = warp_m + i * 16 + g;
                af[i][0] = As[r0    ][kk + tg];
                af[i][1] = As[r0 + 8][kk + tg];
                af[i][2] = As[r0    ][kk + tg + 4];
                af[i][3] = As[r0 + 8][kk + tg + 4];
            }
            #pragma unroll
            for (int j = 0; j < 4; j++) {
                int n0 = warp_n + j * 8 + g;
                bf[j][0] = Bs[n0][kk + tg];
                bf[j][1] = Bs[n0][kk + tg + 4];
            }
            #pragma unroll
            for (int i = 0; i < 4; i++)
                #pragma unroll
                for (int j = 0; j < 4; j++) {
                    asm volatile(
                        "mma.sync.aligned.m16n8k8.row.col.f32.tf32.tf32.f32 "
                        "{%0,%1,%2,%3}, {%4,%5,%6,%7}, {%8,%9}, {%0,%1,%2,%3};"
                        : "+f"(acc[i][j][0]), "+f"(acc[i][j][1]),
                          "+f"(acc[i][j][2]), "+f"(acc[i][j][3])
                        : "r"(af[i][0]), "r"(af[i][1]), "r"(af[i][2]), "r"(af[i][3]),
                          "r"(bf[j][0]), "r"(bf[j][1]));
                }
        }
    }

    // Epilogue: c0/c1 at (row0, col, col+1), c2/c3 at (row0+8, ...)
    #pragma unroll
    for (int i = 0; i < 4; i++) {
        int r0 = brow + warp_m + i * 16 + g;
        #pragma unroll
        for (int j = 0; j < 4; j++) {
            int c = bcol + warp_n + j * 8 + tg * 2;
            float e0 = acc[i][j][0], e1 = acc[i][j][1];
            float e2 = acc[i][j][2], e3 = acc[i][j][3];
            if (EPI == 1) {
                e0 = silu_f(e0); e1 = silu_f(e1);
                e2 = silu_f(e2); e3 = silu_f(e3);
            } else if (EPI == 2) {
                float b0 = bias[c], b1 = bias[c + 1];
                e0 += b0; e1 += b1; e2 += b0; e3 += b1;
            }
            *(float2*)&C[(size_t)r0 * N + c]       = make_float2(e0, e1);
            *(float2*)&C[(size_t)(r0 + 8) * N + c] = make_float2(e2, e3);
        }
    }
}

// ---------------------------------------------------------------------------
// Sequential scan: 128 threads x 8 channels, 1 block per batch.
// One __syncthreads per step via parity-double-buffered warp partial sums.
// ---------------------------------------------------------------------------
__global__ __launch_bounds__(128)
void scan_kernel(const float* __restrict__ h0,
                 const float* __restrict__ log_alpha,
                 float* __restrict__ h_final)
{
    const int b    = blockIdx.x;
    const int tid  = threadIdx.x;
    const int w    = tid >> 5;
    const int lane = tid & 31;
    __shared__ float wsum[2][4];

    const float alpha = expf(log_alpha[0]);

    float h[8];
    *(float4*)(h)     = *(const float4*)&h0[b * DI + tid * 8];
    *(float4*)(h + 4) = *(const float4*)&h0[b * DI + tid * 8 + 4];

    const size_t base = (size_t)b * TT * DI + tid * 8;
    float wx[8];
    *(float4*)(wx)     = *(const float4*)&g_wx[base];
    *(float4*)(wx + 4) = *(const float4*)&g_wx[base + 4];

    for (int t = 0; t < TT; t++) {
        float nx[8];
        if (t + 1 < TT) {
            const size_t nb = base + (size_t)(t + 1) * DI;
            *(float4*)(nx)     = *(const float4*)&g_wx[nb];
            *(float4*)(nx + 4) = *(const float4*)&g_wx[nb + 4];
        }

        #pragma unroll
        for (int i = 0; i < 8; i++) h[i] = fmaf(alpha, wx[i], h[i]);

        // sum of squares: two 4-chains then combine
        float s0 = h[0]*h[0], s1 = h[1]*h[1];
        #pragma unroll
        for (int i = 2; i < 8; i += 2) {
            s0 = fmaf(h[i],   h[i],   s0);
            s1 = fmaf(h[i+1], h[i+1], s1);
        }
        float s = s0 + s1;
        #pragma unroll
        for (int o = 16; o; o >>= 1) s += __shfl_xor_sync(0xffffffffu, s, o);
        if (lane == 0) wsum[t & 1][w] = s;
        __syncthreads();
        float tot = wsum[t & 1][0] + wsum[t & 1][1]
                  + wsum[t & 1][2] + wsum[t & 1][3];
        float r = rsqrtf(tot * (1.0f / DI) + EPS);

        float o8[8];
        #pragma unroll
        for (int i = 0; i < 8; i++) {
            h[i] *= r;
            float sg = 1.0f / (1.0f + __expf(-h[i]));
            o8[i] = h[i] * h[i] * sg;     // h * silu(h)
        }
        float* dst = &g_gate[base + (size_t)t * DI];
        *(float4*)(dst)     = *(float4*)(o8);
        *(float4*)(dst + 4) = *(float4*)(o8 + 4);

        #pragma unroll
        for (int i = 0; i < 8; i++) wx[i] = nx[i];
    }

    if (h_final) {
        *(float4*)&h_final[b * DI + tid * 8]     = *(float4*)(h);
        *(float4*)&h_final[b * DI + tid * 8 + 4] = *(float4*)(h + 4);
    }
}

// ---------------------------------------------------------------------------
extern "C" void kernel_launch(void* const* d_in, const int* in_sizes, int n_in,
                              void* d_out, int out_size)
{
    const float* x         = (const float*)d_in[0];
    const float* h0        = (const float*)d_in[1];
    const float* W_in      = (const float*)d_in[2];
    const float* W_cell    = (const float*)d_in[3];
    const float* b_cell    = (const float*)d_in[4];
    const float* log_alpha = (const float*)d_in[5];
    const float* W_out     = (const float*)d_in[6];

    float* y = (float*)d_out;
    const size_t y_elems = (size_t)MM * DIM;
    float* h_final = ((size_t)out_size >= y_elems + (size_t)BAT * DI)
                         ? y + y_elems : nullptr;

    dim3 block(256);
    dim3 grid(DI / 128, MM / 128);

    // 1) xp = silu(x @ W_in^T)          -> g_xp
    gemm_tf32<1, 0, 0><<<grid, block>>>(x, W_in, nullptr, nullptr, DI, DIM);
    // 2) Wx = xp @ W_cell^T + b_cell    -> g_wx
    gemm_tf32<2, 1, 1><<<grid, block>>>(nullptr, W_cell, b_cell, nullptr, DI, DI);
    // 3) scan                            -> g_gate, h_final
    scan_kernel<<<BAT, 128>>>(h0, log_alpha, h_final);
    // 4) y = gate @ W_out^T             -> d_out
    gemm_tf32<0, 2, 2><<<dim3(DIM / 128, MM / 128), block>>>(nullptr, W_out, nullptr, y, DIM, DI);
}

// round 4
// speedup vs baseline: 1.9586x; 1.5083x over previous
#include <cuda_runtime.h>
#include <math.h>
#include <stdint.h>

#define DIM 1024
#define DI  1024
#define BAT 8
#define TT  2048
#define MM  (BAT*TT)   /* 16384 rows */
#define EPS 1e-6f

// Scratch (device globals; allocation-free per harness rules)
__device__ float g_xa[(size_t)MM * DIM];   // tf32-rounded x
__device__ float g_wi[(size_t)DI * DIM];   // tf32-rounded W_in
__device__ float g_wc[(size_t)DI * DI];    // tf32-rounded W_cell
__device__ float g_wo[(size_t)DIM * DI];   // tf32-rounded W_out
__device__ float g_xp[(size_t)MM * DI];    // silu(x@W_in^T), tf32-rounded
__device__ float g_wx[(size_t)MM * DI];    // xp@W_cell^T + b (full f32)
__device__ float g_gate[(size_t)MM * DI];  // scan output, tf32-rounded

__device__ __forceinline__ float silu_f(float v) {
    return v * (1.0f / (1.0f + __expf(-v)));
}
__device__ __forceinline__ float round_tf32(float f) {
    uint32_t u;
    asm("cvt.rna.tf32.f32 %0, %1;" : "=r"(u) : "f"(f));
    return __uint_as_float(u);
}
__device__ __forceinline__ void cpa16(uint32_t dst, const void* src) {
    asm volatile("cp.async.cg.shared.global [%0], [%1], 16;" :: "r"(dst), "l"(src));
}
#define CP_COMMIT() asm volatile("cp.async.commit_group;" ::: "memory")
#define CP_WAIT1()  asm volatile("cp.async.wait_group 1;"  ::: "memory")

// ---------------------------------------------------------------------------
// Elementwise tf32 pre-round (float4 grid-stride)
// ---------------------------------------------------------------------------
__global__ void round_tf32_kernel(const float* __restrict__ src,
                                  float* __restrict__ dst, int n4)
{
    int i = blockIdx.x * blockDim.x + threadIdx.x;
    if (i >= n4) return;
    float4 v = ((const float4*)src)[i];
    v.x = round_tf32(v.x); v.y = round_tf32(v.y);
    v.z = round_tf32(v.z); v.w = round_tf32(v.w);
    ((float4*)dst)[i] = v;
}

// ---------------------------------------------------------------------------
// TF32 tensor-core GEMM with cp.async 2-stage pipeline.
// C[M,N] = A[M,K] * W[N,K]^T, M=16384, N=K=1024.
// Block 128x128x32, 256 thr = 8 warps (2M x 4N), warp tile 64x32, m16n8k8.
// Operands pre-rounded to tf32 (HW truncation then lossless).
// ID: 0 = GEMM1 (A=g_xa, W=g_wi, silu, ->g_xp rounded)
//     1 = GEMM2 (A=g_xp, W=g_wc, +bias, ->g_wx)
//     2 = GEMM3 (A=g_gate, W=g_wo, none, ->Cout)
// ---------------------------------------------------------------------------
#define PITCH 36                 // smem row pitch (words): conflict-free frags
#define TILE_W (128 * PITCH)     // 4608 words per tile per stage
#define SMEM_WORDS (4 * TILE_W)  // A[2] + B[2]
#define SMEM_BYTES (SMEM_WORDS * 4)

template<int ID>
__global__ __launch_bounds__(256, 2)
void gemm_tc(const float* __restrict__ bias, float* __restrict__ Cout)
{
    extern __shared__ uint32_t sm[];   // [A0 A1 B0 B1], each TILE_W words

    const int K = 1024, N = 1024;
    const float* A = (ID == 0) ? g_xa : (ID == 1) ? g_xp : g_gate;
    const float* W = (ID == 0) ? g_wi : (ID == 1) ? g_wc : g_wo;
    float*       C = (ID == 0) ? g_xp : (ID == 1) ? g_wx : Cout;

    const int tid  = threadIdx.x;
    const int brow = blockIdx.y * 128;
    const int bcol = blockIdx.x * 128;
    const int warp = tid >> 5;
    const int lane = tid & 31;
    const int g    = lane >> 2;
    const int tg   = lane & 3;
    const int warp_m = (warp & 1) * 64;
    const int warp_n = (warp >> 1) * 32;

    const uint32_t smbase = (uint32_t)__cvta_generic_to_shared(sm);

    // load mapping: 1024 float4 per tile, 4 per thread
    const int lr = tid >> 3;             // base row step 32 apart below
    const int lc = (tid & 7) << 2;       // float offset in the 32-wide chunk

    float acc[4][4][4];
    #pragma unroll
    for (int i = 0; i < 4; i++)
        #pragma unroll
        for (int j = 0; j < 4; j++)
            #pragma unroll
            for (int r = 0; r < 4; r++) acc[i][j][r] = 0.f;

    auto load_stage = [&](int s, int ch) {
        const int koff = ch * 32 + lc;
        #pragma unroll
        for (int k = 0; k < 4; k++) {
            int r = lr + k * 32;
            cpa16(smbase + (uint32_t)((s * TILE_W + r * PITCH + lc) * 4),
                  A + (size_t)(brow + r) * K + koff);
            cpa16(smbase + (uint32_t)(((2 + s) * TILE_W + r * PITCH + lc) * 4),
                  W + (size_t)(bcol + r) * K + koff);
        }
        CP_COMMIT();
    };

    load_stage(0, 0);
    load_stage(1, 1);

    const int NCH = K / 32;   // 32
    for (int ch = 0; ch < NCH; ch++) {
        CP_WAIT1();
        __syncthreads();

        const uint32_t* As = sm + (ch & 1) * TILE_W;
        const uint32_t* Bs = sm + (2 + (ch & 1)) * TILE_W;

        #pragma unroll
        for (int ks = 0; ks < 4; ks++) {
            const int kk = ks * 8;
            uint32_t af[4][4], bf[4][2];
            #pragma unroll
            for (int i = 0; i < 4; i++) {
                int r0 = warp_m + i * 16 + g;
                af[i][0] = As[r0 * PITCH + kk + tg];
                af[i][1] = As[(r0 + 8) * PITCH + kk + tg];
                af[i][2] = As[r0 * PITCH + kk + tg + 4];
                af[i][3] = As[(r0 + 8) * PITCH + kk + tg + 4];
            }
            #pragma unroll
            for (int j = 0; j < 4; j++) {
                int n0 = warp_n + j * 8 + g;
                bf[j][0] = Bs[n0 * PITCH + kk + tg];
                bf[j][1] = Bs[n0 * PITCH + kk + tg + 4];
            }
            #pragma unroll
            for (int i = 0; i < 4; i++)
                #pragma unroll
                for (int j = 0; j < 4; j++) {
                    asm volatile(
                        "mma.sync.aligned.m16n8k8.row.col.f32.tf32.tf32.f32 "
                        "{%0,%1,%2,%3}, {%4,%5,%6,%7}, {%8,%9}, {%0,%1,%2,%3};"
                        : "+f"(acc[i][j][0]), "+f"(acc[i][j][1]),
                          "+f"(acc[i][j][2]), "+f"(acc[i][j][3])
                        : "r"(af[i][0]), "r"(af[i][1]), "r"(af[i][2]), "r"(af[i][3]),
                          "r"(bf[j][0]), "r"(bf[j][1]));
                }
        }

        __syncthreads();
        if (ch + 2 < NCH) load_stage(ch & 1, ch + 2);
        else CP_COMMIT();   // keep wait_group accounting consistent
    }

    // Epilogue
    #pragma unroll
    for (int i = 0; i < 4; i++) {
        int r0 = brow + warp_m + i * 16 + g;
        #pragma unroll
        for (int j = 0; j < 4; j++) {
            int c = bcol + warp_n + j * 8 + tg * 2;
            float e0 = acc[i][j][0], e1 = acc[i][j][1];
            float e2 = acc[i][j][2], e3 = acc[i][j][3];
            if (ID == 0) {
                e0 = round_tf32(silu_f(e0)); e1 = round_tf32(silu_f(e1));
                e2 = round_tf32(silu_f(e2)); e3 = round_tf32(silu_f(e3));
            } else if (ID == 1) {
                float b0 = bias[c], b1 = bias[c + 1];
                e0 += b0; e1 += b1; e2 += b0; e3 += b1;
            }
            *(float2*)&C[(size_t)r0 * N + c]       = make_float2(e0, e1);
            *(float2*)&C[(size_t)(r0 + 8) * N + c] = make_float2(e2, e3);
        }
    }
}

// ---------------------------------------------------------------------------
// Sequential scan: 256 threads x 4 channels, 1 block/batch.
// 4-step-deep register prefetch queue; one __syncthreads per step
// (parity double-buffered warp sums). Gate stored tf32-rounded.
// ---------------------------------------------------------------------------
__global__ __launch_bounds__(256)
void scan_kernel(const float* __restrict__ h0,
                 const float* __restrict__ log_alpha,
                 float* __restrict__ h_final)
{
    const int b    = blockIdx.x;
    const int tid  = threadIdx.x;
    const int w    = tid >> 5;
    const int lane = tid & 31;
    __shared__ float wsum[2][8];

    const float alpha = expf(log_alpha[0]);

    float4 hv = *(const float4*)&h0[b * DI + tid * 4];
    float h[4] = {hv.x, hv.y, hv.z, hv.w};

    const size_t base = (size_t)b * TT * DI + tid * 4;
    float4 q[4];
    #pragma unroll
    for (int i = 0; i < 4; i++)
        q[i] = *(const float4*)&g_wx[base + (size_t)i * DI];

    for (int t0 = 0; t0 < TT; t0 += 4) {
        #pragma unroll
        for (int u = 0; u < 4; u++) {
            const int t = t0 + u;

            // issue prefetch for t+4 immediately (4 steps of latency cover)
            float4 nx = make_float4(0.f, 0.f, 0.f, 0.f);
            if (t + 4 < TT)
                nx = *(const float4*)&g_wx[base + (size_t)(t + 4) * DI];

            const float4 cur = q[u];
            h[0] = fmaf(alpha, cur.x, h[0]);
            h[1] = fmaf(alpha, cur.y, h[1]);
            h[2] = fmaf(alpha, cur.z, h[2]);
            h[3] = fmaf(alpha, cur.w, h[3]);

            float s = fmaf(h[0], h[0], h[1] * h[1])
                    + fmaf(h[2], h[2], h[3] * h[3]);
            #pragma unroll
            for (int o = 16; o; o >>= 1)
                s += __shfl_xor_sync(0xffffffffu, s, o);
            if (lane == 0) wsum[t & 1][w] = s;
            __syncthreads();

            const float* ws = wsum[t & 1];
            float tot = ((ws[0] + ws[1]) + (ws[2] + ws[3]))
                      + ((ws[4] + ws[5]) + (ws[6] + ws[7]));
            float r = rsqrtf(tot * (1.0f / DI) + EPS);

            float4 o4;
            #pragma unroll
            for (int i = 0; i < 4; i++) {
                h[i] *= r;
                float sg = 1.0f / (1.0f + __expf(-h[i]));
                float ov = round_tf32(h[i] * h[i] * sg);   // h*silu(h), tf32
                ((float*)&o4)[i] = ov;
            }
            *(float4*)&g_gate[base + (size_t)t * DI] = o4;

            q[u] = nx;
        }
    }

    if (h_final)
        *(float4*)&h_final[b * DI + tid * 4] = make_float4(h[0], h[1], h[2], h[3]);
}

// ---------------------------------------------------------------------------
extern "C" void kernel_launch(void* const* d_in, const int* in_sizes, int n_in,
                              void* d_out, int out_size)
{
    const float* x         = (const float*)d_in[0];
    const float* h0        = (const float*)d_in[1];
    const float* W_in      = (const float*)d_in[2];
    const float* W_cell    = (const float*)d_in[3];
    const float* b_cell    = (const float*)d_in[4];
    const float* log_alpha = (const float*)d_in[5];
    const float* W_out     = (const float*)d_in[6];

    float* y = (float*)d_out;
    const size_t y_elems = (size_t)MM * DIM;
    float* h_final = ((size_t)out_size >= y_elems + (size_t)BAT * DI)
                         ? y + y_elems : nullptr;

    // Allow 72KB dynamic smem (immediate API call, not captured as graph node)
    cudaFuncSetAttribute(gemm_tc<0>, cudaFuncAttributeMaxDynamicSharedMemorySize, SMEM_BYTES);
    cudaFuncSetAttribute(gemm_tc<1>, cudaFuncAttributeMaxDynamicSharedMemorySize, SMEM_BYTES);
    cudaFuncSetAttribute(gemm_tc<2>, cudaFuncAttributeMaxDynamicSharedMemorySize, SMEM_BYTES);

    // Resolve device-global destinations for the pre-round pass
    float *xa, *wi, *wc, *wo;
    cudaGetSymbolAddress((void**)&xa, g_xa);
    cudaGetSymbolAddress((void**)&wi, g_wi);
    cudaGetSymbolAddress((void**)&wc, g_wc);
    cudaGetSymbolAddress((void**)&wo, g_wo);

    // 0) pre-round mma operands to tf32
    {
        int n4x = (MM * DIM) / 4;
        round_tf32_kernel<<<(n4x + 255) / 256, 256>>>(x, xa, n4x);
        int n4w = (DI * DIM) / 4;
        round_tf32_kernel<<<(n4w + 255) / 256, 256>>>(W_in,   wi, n4w);
        round_tf32_kernel<<<(n4w + 255) / 256, 256>>>(W_cell, wc, n4w);
        round_tf32_kernel<<<(n4w + 255) / 256, 256>>>(W_out,  wo, n4w);
    }

    dim3 block(256);
    dim3 grid(DI / 128, MM / 128);

    // 1) xp = silu(x @ W_in^T)          -> g_xp (tf32-rounded)
    gemm_tc<0><<<grid, block, SMEM_BYTES>>>(nullptr, nullptr);
    // 2) Wx = xp @ W_cell^T + b_cell    -> g_wx
    gemm_tc<1><<<grid, block, SMEM_BYTES>>>(b_cell, nullptr);
    // 3) scan                            -> g_gate (tf32-rounded), h_final
    scan_kernel<<<BAT, 256>>>(h0, log_alpha, h_final);
    // 4) y = gate @ W_out^T             -> d_out
    gemm_tc<2><<<dim3(DIM / 128, MM / 128), block, SMEM_BYTES>>>(nullptr, y);
}

// round 6
// speedup vs baseline: 1.9647x; 1.0032x over previous
#include <cuda_runtime.h>
#include <math.h>
#include <stdint.h>

#define DIM 1024
#define DI  1024
#define BAT 8
#define TT  2048
#define MM  (BAT*TT)   /* 16384 rows */
#define EPS 1e-6f

// Scratch (device globals; allocation-free per harness rules)
__device__ float g_xa[(size_t)MM * DIM];   // tf32-rounded x
__device__ float g_wi[(size_t)DI * DIM];   // tf32-rounded W_in
__device__ float g_wc[(size_t)DI * DI];    // tf32-rounded W_cell
__device__ float g_wo[(size_t)DIM * DI];   // tf32-rounded W_out
__device__ float g_xp[(size_t)MM * DI];    // silu(x@W_in^T), tf32-rounded
__device__ float g_wx[(size_t)MM * DI];    // xp@W_cell^T + b (full f32)
__device__ float g_gate[(size_t)MM * DI];  // scan output, tf32-rounded

__device__ __forceinline__ float silu_f(float v) {
    return v * (1.0f / (1.0f + __expf(-v)));
}
__device__ __forceinline__ float round_tf32(float f) {
    uint32_t u;
    asm("cvt.rna.tf32.f32 %0, %1;" : "=r"(u) : "f"(f));
    return __uint_as_float(u);
}
__device__ __forceinline__ float warp_sum(float v) {
    #pragma unroll
    for (int o = 16; o; o >>= 1) v += __shfl_xor_sync(0xffffffffu, v, o);
    return v;
}
__device__ __forceinline__ void cpa16(uint32_t dst, const void* src) {
    asm volatile("cp.async.cg.shared.global [%0], [%1], 16;" :: "r"(dst), "l"(src));
}
#define CP_COMMIT() asm volatile("cp.async.commit_group;" ::: "memory")
#define CP_WAIT2()  asm volatile("cp.async.wait_group 2;"  ::: "memory")

// ---------------------------------------------------------------------------
// Elementwise tf32 pre-round (float4)
// ---------------------------------------------------------------------------
__global__ void round_tf32_kernel(const float* __restrict__ src,
                                  float* __restrict__ dst, int n4)
{
    int i = blockIdx.x * blockDim.x + threadIdx.x;
    if (i >= n4) return;
    float4 v = ((const float4*)src)[i];
    v.x = round_tf32(v.x); v.y = round_tf32(v.y);
    v.z = round_tf32(v.z); v.w = round_tf32(v.w);
    ((float4*)dst)[i] = v;
}

// ---------------------------------------------------------------------------
// TF32 tensor-core GEMM, 3-stage cp.async pipeline.
// C[M,N] = A[M,K] * W[N,K]^T, M=16384, N=K=1024.
// Block 128x128x32, 256 thr = 8 warps (2M x 4N), warp tile 64x32, m16n8k8.
// Operands pre-rounded to tf32 (HW truncation is then lossless).
// ID: 0 = GEMM1 (A=g_xa, W=g_wi, silu, ->g_xp rounded)
//     1 = GEMM2 (A=g_xp, W=g_wc, +bias, ->g_wx)
//     2 = GEMM3 (A=g_gate, W=g_wo, none, ->Cout)
// ---------------------------------------------------------------------------
#define PITCH 36                 // smem row pitch (words): conflict-free frags
#define TILE_W (128 * PITCH)     // 4608 words per tile per stage
#define NSTAGE 3
#define SMEM_WORDS (2 * NSTAGE * TILE_W)   // A[3] + B[3]
#define SMEM_BYTES (SMEM_WORDS * 4)        // 110592 B

template<int ID>
__global__ __launch_bounds__(256, 2)
void gemm_tc(const float* __restrict__ bias, float* __restrict__ Cout)
{
    extern __shared__ uint32_t sm[];   // [A0 A1 A2 B0 B1 B2]

    const int K = 1024, N = 1024;
    const float* A = (ID == 0) ? g_xa : (ID == 1) ? g_xp : g_gate;
    const float* W = (ID == 0) ? g_wi : (ID == 1) ? g_wc : g_wo;
    float*       C = (ID == 0) ? g_xp : (ID == 1) ? g_wx : Cout;

    const int tid  = threadIdx.x;
    const int brow = blockIdx.y * 128;
    const int bcol = blockIdx.x * 128;
    const int warp = tid >> 5;
    const int lane = tid & 31;
    const int g    = lane >> 2;
    const int tg   = lane & 3;
    const int warp_m = (warp & 1) * 64;
    const int warp_n = (warp >> 1) * 32;

    const uint32_t smbase = (uint32_t)__cvta_generic_to_shared(sm);

    // load mapping: 1024 float4 per tile, 4 per thread
    const int lr = tid >> 3;             // rows stepped by 32
    const int lc = (tid & 7) << 2;       // float offset within 32-wide chunk

    float acc[4][4][4];
    #pragma unroll
    for (int i = 0; i < 4; i++)
        #pragma unroll
        for (int j = 0; j < 4; j++)
            #pragma unroll
            for (int r = 0; r < 4; r++) acc[i][j][r] = 0.f;

    auto load_stage = [&](int s, int ch) {
        const int koff = ch * 32 + lc;
        #pragma unroll
        for (int k = 0; k < 4; k++) {
            int r = lr + k * 32;
            cpa16(smbase + (uint32_t)((s * TILE_W + r * PITCH + lc) * 4),
                  A + (size_t)(brow + r) * K + koff);
            cpa16(smbase + (uint32_t)(((NSTAGE + s) * TILE_W + r * PITCH + lc) * 4),
                  W + (size_t)(bcol + r) * K + koff);
        }
        CP_COMMIT();
    };

    load_stage(0, 0);
    load_stage(1, 1);
    load_stage(2, 2);

    const int NCH = K / 32;   // 32
    for (int ch = 0; ch < NCH; ch++) {
        CP_WAIT2();           // group 'ch' complete (2 newest may be pending)
        __syncthreads();

        const int s = ch % NSTAGE;
        const uint32_t* As = sm + s * TILE_W;
        const uint32_t* Bs = sm + (NSTAGE + s) * TILE_W;

        #pragma unroll
        for (int ks = 0; ks < 4; ks++) {
            const int kk = ks * 8;
            uint32_t af[4][4], bf[4][2];
            #pragma unroll
            for (int i = 0; i < 4; i++) {
                int r0 = warp_m + i * 16 + g;
                af[i][0] = As[r0 * PITCH + kk + tg];
                af[i][1] = As[(r0 + 8) * PITCH + kk + tg];
                af[i][2] = As[r0 * PITCH + kk + tg + 4];
                af[i][3] = As[(r0 + 8) * PITCH + kk + tg + 4];
            }
            #pragma unroll
            for (int j = 0; j < 4; j++) {
                int n0 = warp_n + j * 8 + g;
                bf[j][0] = Bs[n0 * PITCH + kk + tg];
                bf[j][1] = Bs[n0 * PITCH + kk + tg + 4];
            }
            #pragma unroll
            for (int i = 0; i < 4; i++)
                #pragma unroll
                for (int j = 0; j < 4; j++) {
                    asm volatile(
                        "mma.sync.aligned.m16n8k8.row.col.f32.tf32.tf32.f32 "
                        "{%0,%1,%2,%3}, {%4,%5,%6,%7}, {%8,%9}, {%0,%1,%2,%3};"
                        : "+f"(acc[i][j][0]), "+f"(acc[i][j][1]),
                          "+f"(acc[i][j][2]), "+f"(acc[i][j][3])
                        : "r"(af[i][0]), "r"(af[i][1]), "r"(af[i][2]), "r"(af[i][3]),
                          "r"(bf[j][0]), "r"(bf[j][1]));
                }
        }

        __syncthreads();
        if (ch + NSTAGE < NCH) load_stage(s, ch + NSTAGE);
        else CP_COMMIT();   // empty group keeps wait_group accounting aligned
    }

    // Epilogue
    #pragma unroll
    for (int i = 0; i < 4; i++) {
        int r0 = brow + warp_m + i * 16 + g;
        #pragma unroll
        for (int j = 0; j < 4; j++) {
            int c = bcol + warp_n + j * 8 + tg * 2;
            float e0 = acc[i][j][0], e1 = acc[i][j][1];
            float e2 = acc[i][j][2], e3 = acc[i][j][3];
            if (ID == 0) {
                e0 = round_tf32(silu_f(e0)); e1 = round_tf32(silu_f(e1));
                e2 = round_tf32(silu_f(e2)); e3 = round_tf32(silu_f(e3));
            } else if (ID == 1) {
                float b0 = bias[c], b1 = bias[c + 1];
                e0 += b0; e1 += b1; e2 += b0; e3 += b1;
            }
            *(float2*)&C[(size_t)r0 * N + c]       = make_float2(e0, e1);
            *(float2*)&C[(size_t)(r0 + 8) * N + c] = make_float2(e2, e3);
        }
    }
}

// ---------------------------------------------------------------------------
// Sequential scan: 256 threads x 4 channels, 1 block/batch.
// 8-step register prefetch queue; shfl-tree warp reduction;
// one __syncthreads per step (parity double-buffered warp sums).
// ---------------------------------------------------------------------------
__global__ __launch_bounds__(256)
void scan_kernel(const float* __restrict__ h0,
                 const float* __restrict__ log_alpha,
                 float* __restrict__ h_final)
{
    const int b    = blockIdx.x;
    const int tid  = threadIdx.x;
    const int w    = tid >> 5;
    const int lane = tid & 31;
    __shared__ __align__(16) float wsum[2][8];

    const float alpha = expf(log_alpha[0]);

    float4 hv = *(const float4*)&h0[b * DI + tid * 4];
    float h[4] = {hv.x, hv.y, hv.z, hv.w};

    const size_t base = (size_t)b * TT * DI + tid * 4;
    float4 q[8];
    #pragma unroll
    for (int i = 0; i < 8; i++)
        q[i] = *(const float4*)&g_wx[base + (size_t)i * DI];

    for (int t0 = 0; t0 < TT; t0 += 8) {
        #pragma unroll
        for (int u = 0; u < 8; u++) {
            const int t = t0 + u;

            // prefetch for t+8 (window ~8 steps of latency cover)
            float4 nx = make_float4(0.f, 0.f, 0.f, 0.f);
            if (t + 8 < TT)
                nx = *(const float4*)&g_wx[base + (size_t)(t + 8) * DI];

            const float4 cur = q[u];
            h[0] = fmaf(alpha, cur.x, h[0]);
            h[1] = fmaf(alpha, cur.y, h[1]);
            h[2] = fmaf(alpha, cur.z, h[2]);
            h[3] = fmaf(alpha, cur.w, h[3]);

            float s = fmaf(h[0], h[0], h[1] * h[1])
                    + fmaf(h[2], h[2], h[3] * h[3]);
            s = warp_sum(s);
            if (lane == 0) wsum[t & 1][w] = s;
            __syncthreads();

            float4 w0 = *(const float4*)&wsum[t & 1][0];
            float4 w1 = *(const float4*)&wsum[t & 1][4];
            float tot = ((w0.x + w0.y) + (w0.z + w0.w))
                      + ((w1.x + w1.y) + (w1.z + w1.w));
            float r = rsqrtf(tot * (1.0f / DI) + EPS);

            float4 o4;
            #pragma unroll
            for (int i = 0; i < 4; i++) {
                h[i] *= r;
                float sg = 1.0f / (1.0f + __expf(-h[i]));
                ((float*)&o4)[i] = round_tf32(h[i] * h[i] * sg);  // h*silu(h)
            }
            *(float4*)&g_gate[base + (size_t)t * DI] = o4;

            q[u] = nx;
        }
    }

    if (h_final)
        *(float4*)&h_final[b * DI + tid * 4] = make_float4(h[0], h[1], h[2], h[3]);
}

// ---------------------------------------------------------------------------
extern "C" void kernel_launch(void* const* d_in, const int* in_sizes, int n_in,
                              void* d_out, int out_size)
{
    const float* x         = (const float*)d_in[0];
    const float* h0        = (const float*)d_in[1];
    const float* W_in      = (const float*)d_in[2];
    const float* W_cell    = (const float*)d_in[3];
    const float* b_cell    = (const float*)d_in[4];
    const float* log_alpha = (const float*)d_in[5];
    const float* W_out     = (const float*)d_in[6];

    float* y = (float*)d_out;
    const size_t y_elems = (size_t)MM * DIM;
    float* h_final = ((size_t)out_size >= y_elems + (size_t)BAT * DI)
                         ? y + y_elems : nullptr;

    cudaFuncSetAttribute(gemm_tc<0>, cudaFuncAttributeMaxDynamicSharedMemorySize, SMEM_BYTES);
    cudaFuncSetAttribute(gemm_tc<1>, cudaFuncAttributeMaxDynamicSharedMemorySize, SMEM_BYTES);
    cudaFuncSetAttribute(gemm_tc<2>, cudaFuncAttributeMaxDynamicSharedMemorySize, SMEM_BYTES);

    float *xa, *wi, *wc, *wo;
    cudaGetSymbolAddress((void**)&xa, g_xa);
    cudaGetSymbolAddress((void**)&wi, g_wi);
    cudaGetSymbolAddress((void**)&wc, g_wc);
    cudaGetSymbolAddress((void**)&wo, g_wo);

    // 0) pre-round mma operands to tf32
    {
        int n4x = (MM * DIM) / 4;
        round_tf32_kernel<<<(n4x + 255) / 256, 256>>>(x, xa, n4x);
        int n4w = (DI * DIM) / 4;
        round_tf32_kernel<<<(n4w + 255) / 256, 256>>>(W_in,   wi, n4w);
        round_tf32_kernel<<<(n4w + 255) / 256, 256>>>(W_cell, wc, n4w);
        round_tf32_kernel<<<(n4w + 255) / 256, 256>>>(W_out,  wo, n4w);
    }

    dim3 block(256);
    dim3 grid(DI / 128, MM / 128);

    // 1) xp = silu(x @ W_in^T)          -> g_xp (tf32-rounded)
    gemm_tc<0><<<grid, block, SMEM_BYTES>>>(nullptr, nullptr);
    // 2) Wx = xp @ W_cell^T + b_cell    -> g_wx
    gemm_tc<1><<<grid, block, SMEM_BYTES>>>(b_cell, nullptr);
    // 3) scan                            -> g_gate (tf32-rounded), h_final
    scan_kernel<<<BAT, 256>>>(h0, log_alpha, h_final);
    // 4) y = gate @ W_out^T             -> d_out
    gemm_tc<2><<<dim3(DIM / 128, MM / 128), block, SMEM_BYTES>>>(nullptr, y);
}

// round 7
// speedup vs baseline: 2.4144x; 1.2289x over previous
#include <cuda_runtime.h>
#include <cuda_fp16.h>
#include <math.h>
#include <stdint.h>

#define DIM 1024
#define DI  1024
#define BAT 8
#define TT  2048
#define MM  (BAT*TT)   /* 16384 rows */
#define EPS 1e-6f

// Scratch (device globals; allocation-free per harness rules)
__device__ __half g_xa[(size_t)MM * DIM];   // fp16 x
__device__ __half g_wi[(size_t)DI * DIM];   // fp16 W_in
__device__ __half g_wc[(size_t)DI * DI];    // fp16 W_cell
__device__ __half g_wo[(size_t)DIM * DI];   // fp16 W_out
__device__ __half g_xp[(size_t)MM * DI];    // silu(x@W_in^T), fp16
__device__ float  g_wx[(size_t)MM * DI];    // xp@W_cell^T + b (fp32)
__device__ __half g_gate[(size_t)MM * DI];  // scan output, fp16

__device__ __forceinline__ float silu_f(float v) {
    return v * (1.0f / (1.0f + __expf(-v)));
}
__device__ __forceinline__ float warp_sum(float v) {
    #pragma unroll
    for (int o = 16; o; o >>= 1) v += __shfl_xor_sync(0xffffffffu, v, o);
    return v;
}
__device__ __forceinline__ void cpa16(uint32_t dst, const void* src) {
    asm volatile("cp.async.cg.shared.global [%0], [%1], 16;" :: "r"(dst), "l"(src));
}
#define CP_COMMIT() asm volatile("cp.async.commit_group;" ::: "memory")
#define CP_WAIT3()  asm volatile("cp.async.wait_group 3;"  ::: "memory")

__device__ __forceinline__ void ldsm4(uint32_t& r0, uint32_t& r1,
                                      uint32_t& r2, uint32_t& r3, uint32_t addr) {
    asm volatile("ldmatrix.sync.aligned.m8n8.x4.shared.b16 {%0,%1,%2,%3}, [%4];"
                 : "=r"(r0), "=r"(r1), "=r"(r2), "=r"(r3) : "r"(addr));
}

// ---------------------------------------------------------------------------
// fp32 -> fp16 conversion (float4 -> 4 halves)
// ---------------------------------------------------------------------------
__global__ void to_half_kernel(const float* __restrict__ src,
                               __half* __restrict__ dst, int n4)
{
    int i = blockIdx.x * blockDim.x + threadIdx.x;
    if (i >= n4) return;
    float4 v = ((const float4*)src)[i];
    __half2 h01 = __floats2half2_rn(v.x, v.y);
    __half2 h23 = __floats2half2_rn(v.z, v.w);
    uint2 p;
    p.x = *(uint32_t*)&h01;
    p.y = *(uint32_t*)&h23;
    ((uint2*)dst)[i] = p;
}

// ---------------------------------------------------------------------------
// fp16 tensor-core GEMM, ldmatrix fragments, 4-stage cp.async pipeline.
// C[M,N] = A[M,K] * W[N,K]^T, M=16384, N=K=1024, fp32 accumulate.
// Block 128x128x32, 256 thr = 8 warps (2M x 4N), warp tile 64x32, m16n8k16.
// ID: 0 = GEMM1 (A=g_xa, W=g_wi, silu -> g_xp fp16)
//     1 = GEMM2 (A=g_xp, W=g_wc, +bias -> g_wx fp32)
//     2 = GEMM3 (A=g_gate, W=g_wo -> Cout fp32)
// ---------------------------------------------------------------------------
#define PITCH_H 40                   // halves per smem row (80B, conflict-free)
#define TILE_H  (128 * PITCH_H)      // 5120 halves = 10240 B per tile
#define NSTAGE  4
#define SMEM_BYTES (2 * NSTAGE * TILE_H * 2)   // 81920 B

template<int ID>
__global__ __launch_bounds__(256, 2)
void gemm_hc(const float* __restrict__ bias, float* __restrict__ Cout)
{
    extern __shared__ __half smh[];   // [A0..A3 B0..B3]

    const int K = 1024, N = 1024;
    const __half* A = (ID == 0) ? g_xa : (ID == 1) ? g_xp : g_gate;
    const __half* W = (ID == 0) ? g_wi : (ID == 1) ? g_wc : g_wo;

    const int tid  = threadIdx.x;
    const int brow = blockIdx.y * 128;
    const int bcol = blockIdx.x * 128;
    const int warp = tid >> 5;
    const int lane = tid & 31;
    const int g    = lane >> 2;
    const int tg   = lane & 3;
    const int warp_m = (warp & 1) * 64;
    const int warp_n = (warp >> 1) * 32;

    const uint32_t smbase = (uint32_t)__cvta_generic_to_shared(smh);

    // cp.async mapping: per tile 128 rows x 64B = 512 x 16B, 2 per thread
    const int r0l = tid >> 2;        // row for idx=tid
    const int c0l = tid & 3;         // 16B unit within row

    // ldmatrix lane address components (in halves)
    const int a_row = warp_m + (lane & 15);
    const int a_kof = (lane >> 4) * 8;
    const int b_row = warp_n + (lane & 7) + ((lane >> 4) & 1) * 8;
    const int b_kof = ((lane >> 3) & 1) * 8;

    float acc[4][4][4];
    #pragma unroll
    for (int i = 0; i < 4; i++)
        #pragma unroll
        for (int j = 0; j < 4; j++)
            #pragma unroll
            for (int r = 0; r < 4; r++) acc[i][j][r] = 0.f;

    auto load_stage = [&](int s, int ch) {
        const int k0 = ch * 32;
        #pragma unroll
        for (int i = 0; i < 2; i++) {
            int r = r0l + i * 64;
            cpa16(smbase + (uint32_t)(((s * TILE_H) + r * PITCH_H) * 2 + c0l * 16),
                  A + (size_t)(brow + r) * K + k0 + c0l * 8);
            cpa16(smbase + (uint32_t)((((NSTAGE + s) * TILE_H) + r * PITCH_H) * 2 + c0l * 16),
                  W + (size_t)(bcol + r) * K + k0 + c0l * 8);
        }
        CP_COMMIT();
    };

    load_stage(0, 0);
    load_stage(1, 1);
    load_stage(2, 2);
    load_stage(3, 3);

    const int NCH = K / 32;   // 32
    for (int ch = 0; ch < NCH; ch++) {
        CP_WAIT3();
        __syncthreads();

        const int s = ch & (NSTAGE - 1);
        const uint32_t aT = smbase + (uint32_t)(s * TILE_H * 2);
        const uint32_t bT = smbase + (uint32_t)((NSTAGE + s) * TILE_H * 2);

        #pragma unroll
        for (int ks = 0; ks < 2; ks++) {
            const int kk = ks * 16;
            uint32_t af[4][4], bf[2][4];
            #pragma unroll
            for (int i = 0; i < 4; i++)
                ldsm4(af[i][0], af[i][1], af[i][2], af[i][3],
                      aT + (uint32_t)(((a_row + i * 16) * PITCH_H + kk + a_kof) * 2));
            #pragma unroll
            for (int j2 = 0; j2 < 2; j2++)
                ldsm4(bf[j2][0], bf[j2][1], bf[j2][2], bf[j2][3],
                      bT + (uint32_t)(((b_row + j2 * 16) * PITCH_H + kk + b_kof) * 2));

            #pragma unroll
            for (int i = 0; i < 4; i++)
                #pragma unroll
                for (int j = 0; j < 4; j++) {
                    const uint32_t bb0 = bf[j >> 1][(j & 1) * 2];
                    const uint32_t bb1 = bf[j >> 1][(j & 1) * 2 + 1];
                    asm volatile(
                        "mma.sync.aligned.m16n8k16.row.col.f32.f16.f16.f32 "
                        "{%0,%1,%2,%3}, {%4,%5,%6,%7}, {%8,%9}, {%0,%1,%2,%3};"
                        : "+f"(acc[i][j][0]), "+f"(acc[i][j][1]),
                          "+f"(acc[i][j][2]), "+f"(acc[i][j][3])
                        : "r"(af[i][0]), "r"(af[i][1]), "r"(af[i][2]), "r"(af[i][3]),
                          "r"(bb0), "r"(bb1));
                }
        }

        __syncthreads();
        if (ch + NSTAGE < NCH) load_stage(s, ch + NSTAGE);
        else CP_COMMIT();   // empty group keeps wait accounting aligned
    }

    // Epilogue
    #pragma unroll
    for (int i = 0; i < 4; i++) {
        int r0 = brow + warp_m + i * 16 + g;
        #pragma unroll
        for (int j = 0; j < 4; j++) {
            int c = bcol + warp_n + j * 8 + tg * 2;
            float e0 = acc[i][j][0], e1 = acc[i][j][1];
            float e2 = acc[i][j][2], e3 = acc[i][j][3];
            if (ID == 0) {
                // silu then fp16 for GEMM2 input
                __half2 lo = __floats2half2_rn(silu_f(e0), silu_f(e1));
                __half2 hi = __floats2half2_rn(silu_f(e2), silu_f(e3));
                *(__half2*)&g_xp[(size_t)r0 * N + c]       = lo;
                *(__half2*)&g_xp[(size_t)(r0 + 8) * N + c] = hi;
            } else if (ID == 1) {
                float b0 = bias[c], b1 = bias[c + 1];
                *(float2*)&g_wx[(size_t)r0 * N + c]       = make_float2(e0 + b0, e1 + b1);
                *(float2*)&g_wx[(size_t)(r0 + 8) * N + c] = make_float2(e2 + b0, e3 + b1);
            } else {
                *(float2*)&Cout[(size_t)r0 * N + c]       = make_float2(e0, e1);
                *(float2*)&Cout[(size_t)(r0 + 8) * N + c] = make_float2(e2, e3);
            }
        }
    }
}

// ---------------------------------------------------------------------------
// Sequential scan: 256 threads x 4 channels, 1 block/batch.
// 8-step register prefetch queue; shfl-tree warp reduction;
// one __syncthreads per step (parity double-buffered warp sums).
// Gate stored as fp16 (GEMM3 input).
// ---------------------------------------------------------------------------
__global__ __launch_bounds__(256)
void scan_kernel(const float* __restrict__ h0,
                 const float* __restrict__ log_alpha,
                 float* __restrict__ h_final)
{
    const int b    = blockIdx.x;
    const int tid  = threadIdx.x;
    const int w    = tid >> 5;
    const int lane = tid & 31;
    __shared__ __align__(16) float wsum[2][8];

    const float alpha = expf(log_alpha[0]);

    float4 hv = *(const float4*)&h0[b * DI + tid * 4];
    float h[4] = {hv.x, hv.y, hv.z, hv.w};

    const size_t base = (size_t)b * TT * DI + tid * 4;
    float4 q[8];
    #pragma unroll
    for (int i = 0; i < 8; i++)
        q[i] = *(const float4*)&g_wx[base + (size_t)i * DI];

    for (int t0 = 0; t0 < TT; t0 += 8) {
        #pragma unroll
        for (int u = 0; u < 8; u++) {
            const int t = t0 + u;

            float4 nx = make_float4(0.f, 0.f, 0.f, 0.f);
            if (t + 8 < TT)
                nx = *(const float4*)&g_wx[base + (size_t)(t + 8) * DI];

            const float4 cur = q[u];
            h[0] = fmaf(alpha, cur.x, h[0]);
            h[1] = fmaf(alpha, cur.y, h[1]);
            h[2] = fmaf(alpha, cur.z, h[2]);
            h[3] = fmaf(alpha, cur.w, h[3]);

            float s = fmaf(h[0], h[0], h[1] * h[1])
                    + fmaf(h[2], h[2], h[3] * h[3]);
            s = warp_sum(s);
            if (lane == 0) wsum[t & 1][w] = s;
            __syncthreads();

            float4 w0 = *(const float4*)&wsum[t & 1][0];
            float4 w1 = *(const float4*)&wsum[t & 1][4];
            float tot = ((w0.x + w0.y) + (w0.z + w0.w))
                      + ((w1.x + w1.y) + (w1.z + w1.w));
            float r = rsqrtf(tot * (1.0f / DI) + EPS);

            float o4[4];
            #pragma unroll
            for (int i = 0; i < 4; i++) {
                h[i] *= r;
                float sg = 1.0f / (1.0f + __expf(-h[i]));
                o4[i] = h[i] * h[i] * sg;   // h * silu(h)
            }
            __half2 p01 = __floats2half2_rn(o4[0], o4[1]);
            __half2 p23 = __floats2half2_rn(o4[2], o4[3]);
            uint2 pk; pk.x = *(uint32_t*)&p01; pk.y = *(uint32_t*)&p23;
            *(uint2*)&g_gate[base + (size_t)t * DI] = pk;

            q[u] = nx;
        }
    }

    if (h_final)
        *(float4*)&h_final[b * DI + tid * 4] = make_float4(h[0], h[1], h[2], h[3]);
}

// ---------------------------------------------------------------------------
extern "C" void kernel_launch(void* const* d_in, const int* in_sizes, int n_in,
                              void* d_out, int out_size)
{
    const float* x         = (const float*)d_in[0];
    const float* h0        = (const float*)d_in[1];
    const float* W_in      = (const float*)d_in[2];
    const float* W_cell    = (const float*)d_in[3];
    const float* b_cell    = (const float*)d_in[4];
    const float* log_alpha = (const float*)d_in[5];
    const float* W_out     = (const float*)d_in[6];

    float* y = (float*)d_out;
    const size_t y_elems = (size_t)MM * DIM;
    float* h_final = ((size_t)out_size >= y_elems + (size_t)BAT * DI)
                         ? y + y_elems : nullptr;

    cudaFuncSetAttribute(gemm_hc<0>, cudaFuncAttributeMaxDynamicSharedMemorySize, SMEM_BYTES);
    cudaFuncSetAttribute(gemm_hc<1>, cudaFuncAttributeMaxDynamicSharedMemorySize, SMEM_BYTES);
    cudaFuncSetAttribute(gemm_hc<2>, cudaFuncAttributeMaxDynamicSharedMemorySize, SMEM_BYTES);

    __half *xa, *wi, *wc, *wo;
    cudaGetSymbolAddress((void**)&xa, g_xa);
    cudaGetSymbolAddress((void**)&wi, g_wi);
    cudaGetSymbolAddress((void**)&wc, g_wc);
    cudaGetSymbolAddress((void**)&wo, g_wo);

    // 0) convert mma operands to fp16
    {
        int n4x = (MM * DIM) / 4;
        to_half_kernel<<<(n4x + 255) / 256, 256>>>(x, xa, n4x);
        int n4w = (DI * DIM) / 4;
        to_half_kernel<<<(n4w + 255) / 256, 256>>>(W_in,   wi, n4w);
        to_half_kernel<<<(n4w + 255) / 256, 256>>>(W_cell, wc, n4w);
        to_half_kernel<<<(n4w + 255) / 256, 256>>>(W_out,  wo, n4w);
    }

    dim3 block(256);
    dim3 grid(DI / 128, MM / 128);

    // 1) xp = silu(x @ W_in^T)          -> g_xp (fp16)
    gemm_hc<0><<<grid, block, SMEM_BYTES>>>(nullptr, nullptr);
    // 2) Wx = xp @ W_cell^T + b_cell    -> g_wx (fp32)
    gemm_hc<1><<<grid, block, SMEM_BYTES>>>(b_cell, nullptr);
    // 3) scan                            -> g_gate (fp16), h_final
    scan_kernel<<<BAT, 256>>>(h0, log_alpha, h_final);
    // 4) y = gate @ W_out^T             -> d_out
    gemm_hc<2><<<dim3(DIM / 128, MM / 128), block, SMEM_BYTES>>>(nullptr, y);
}

// round 8
// speedup vs baseline: 3.6164x; 1.4978x over previous
#include <cuda_runtime.h>
#include <cuda_fp16.h>
#include <math.h>
#include <stdint.h>

#define DIM 1024
#define DI  1024
#define BAT 8
#define TT  2048
#define MM  (BAT*TT)   /* 16384 rows */
#define EPS 1e-6f

// Scratch (device globals; allocation-free per harness rules)
__device__ __half g_xa[(size_t)MM * DIM];   // fp16 x
__device__ __half g_wi[(size_t)DI * DIM];   // fp16 W_in
__device__ __half g_wc[(size_t)DI * DI];    // fp16 W_cell
__device__ __half g_wo[(size_t)DIM * DI];   // fp16 W_out
__device__ __half g_xp[(size_t)MM * DI];    // silu(x@W_in^T), fp16
__device__ float  g_wx[(size_t)MM * DI];    // xp@W_cell^T + b (fp32)
__device__ __half g_gate[(size_t)MM * DI];  // scan output, fp16

__device__ __forceinline__ float silu_f(float v) {
    return __fdividef(v, 1.0f + __expf(-v));
}
__device__ __forceinline__ float warp_sum(float v) {
    #pragma unroll
    for (int o = 16; o; o >>= 1) v += __shfl_xor_sync(0xffffffffu, v, o);
    return v;
}
__device__ __forceinline__ void cpa16(uint32_t dst, const void* src) {
    asm volatile("cp.async.cg.shared.global [%0], [%1], 16;" :: "r"(dst), "l"(src));
}
#define CP_COMMIT() asm volatile("cp.async.commit_group;" ::: "memory")
#define CP_WAIT2()  asm volatile("cp.async.wait_group 2;"  ::: "memory")

__device__ __forceinline__ void ldsm4(uint32_t& r0, uint32_t& r1,
                                      uint32_t& r2, uint32_t& r3, uint32_t addr) {
    asm volatile("ldmatrix.sync.aligned.m8n8.x4.shared.b16 {%0,%1,%2,%3}, [%4];"
                 : "=r"(r0), "=r"(r1), "=r"(r2), "=r"(r3) : "r"(addr));
}

// ---------------------------------------------------------------------------
// fp32 -> fp16 conversion
// ---------------------------------------------------------------------------
__global__ void to_half_kernel(const float* __restrict__ src,
                               __half* __restrict__ dst, int n4)
{
    int i = blockIdx.x * blockDim.x + threadIdx.x;
    if (i >= n4) return;
    float4 v = ((const float4*)src)[i];
    __half2 h01 = __floats2half2_rn(v.x, v.y);
    __half2 h23 = __floats2half2_rn(v.z, v.w);
    uint2 p;
    p.x = *(uint32_t*)&h01;
    p.y = *(uint32_t*)&h23;
    ((uint2*)dst)[i] = p;
}

// ---------------------------------------------------------------------------
// fp16 tensor-core GEMM, ldmatrix fragments, 4-slot cp.async pipeline,
// ONE barrier per chunk, loads lead compute by 3 chunks.
// C[M,N] = A[M,K] * W[N,K]^T, M=16384, N=K=1024, fp32 accumulate.
// Block 128x128x32, 256 thr = 8 warps (2M x 4N), warp tile 64x32, m16n8k16.
// ID: 0 = GEMM1 (silu -> g_xp fp16), 1 = GEMM2 (+bias -> g_wx fp32),
//     2 = GEMM3 (-> Cout fp32)
// ---------------------------------------------------------------------------
#define PITCH_H 40                   // halves per smem row (80B, conflict-free)
#define TILE_H  (128 * PITCH_H)      // 5120 halves per tile
#define NSTAGE  4
#define SMEM_BYTES (2 * NSTAGE * TILE_H * 2)   // 81920 B

template<int ID>
__global__ __launch_bounds__(256, 2)
void gemm_hc(const float* __restrict__ bias, float* __restrict__ Cout)
{
    extern __shared__ __half smh[];   // [A0..A3 B0..B3]

    const int K = 1024, N = 1024;
    const __half* A = (ID == 0) ? g_xa : (ID == 1) ? g_xp : g_gate;
    const __half* W = (ID == 0) ? g_wi : (ID == 1) ? g_wc : g_wo;

    const int tid  = threadIdx.x;
    const int brow = blockIdx.y * 128;
    const int bcol = blockIdx.x * 128;
    const int warp = tid >> 5;
    const int lane = tid & 31;
    const int g    = lane >> 2;
    const int tg   = lane & 3;
    const int warp_m = (warp & 1) * 64;
    const int warp_n = (warp >> 1) * 32;

    const uint32_t smbase = (uint32_t)__cvta_generic_to_shared(smh);

    // cp.async mapping: per tile 128 rows x 64B = 512 x 16B, 2 per thread
    const int r0l = tid >> 2;
    const int c0l = tid & 3;

    // ldmatrix lane address components
    const int a_row = warp_m + (lane & 15);
    const int a_kof = (lane >> 4) * 8;
    const int b_row = warp_n + (lane & 7) + ((lane >> 4) & 1) * 8;
    const int b_kof = ((lane >> 3) & 1) * 8;

    float acc[4][4][4];
    #pragma unroll
    for (int i = 0; i < 4; i++)
        #pragma unroll
        for (int j = 0; j < 4; j++)
            #pragma unroll
            for (int r = 0; r < 4; r++) acc[i][j][r] = 0.f;

    auto load_stage = [&](int s, int ch) {
        const int k0 = ch * 32;
        #pragma unroll
        for (int i = 0; i < 2; i++) {
            int r = r0l + i * 64;
            cpa16(smbase + (uint32_t)(((s * TILE_H) + r * PITCH_H) * 2 + c0l * 16),
                  A + (size_t)(brow + r) * K + k0 + c0l * 8);
            cpa16(smbase + (uint32_t)((((NSTAGE + s) * TILE_H) + r * PITCH_H) * 2 + c0l * 16),
                  W + (size_t)(bcol + r) * K + k0 + c0l * 8);
        }
        CP_COMMIT();
    };

    // prologue: 3 chunks in flight (slots 0..2)
    load_stage(0, 0);
    load_stage(1, 1);
    load_stage(2, 2);

    const int NCH = K / 32;   // 32
    for (int ch = 0; ch < NCH; ch++) {
        CP_WAIT2();           // group for chunk ch complete
        __syncthreads();      // all warps finished chunk ch-1 -> its slot free

        // issue load for chunk ch+3 into slot (ch+3)&3 == (ch-1)&3
        if (ch + 3 < NCH) load_stage((ch + 3) & (NSTAGE - 1), ch + 3);
        else CP_COMMIT();     // empty group keeps wait accounting aligned

        const int s = ch & (NSTAGE - 1);
        const uint32_t aT = smbase + (uint32_t)(s * TILE_H * 2);
        const uint32_t bT = smbase + (uint32_t)((NSTAGE + s) * TILE_H * 2);

        #pragma unroll
        for (int ks = 0; ks < 2; ks++) {
            const int kk = ks * 16;
            uint32_t af[4][4], bf[2][4];
            #pragma unroll
            for (int i = 0; i < 4; i++)
                ldsm4(af[i][0], af[i][1], af[i][2], af[i][3],
                      aT + (uint32_t)(((a_row + i * 16) * PITCH_H + kk + a_kof) * 2));
            #pragma unroll
            for (int j2 = 0; j2 < 2; j2++)
                ldsm4(bf[j2][0], bf[j2][1], bf[j2][2], bf[j2][3],
                      bT + (uint32_t)(((b_row + j2 * 16) * PITCH_H + kk + b_kof) * 2));

            #pragma unroll
            for (int i = 0; i < 4; i++)
                #pragma unroll
                for (int j = 0; j < 4; j++) {
                    const uint32_t bb0 = bf[j >> 1][(j & 1) * 2];
                    const uint32_t bb1 = bf[j >> 1][(j & 1) * 2 + 1];
                    asm volatile(
                        "mma.sync.aligned.m16n8k16.row.col.f32.f16.f16.f32 "
                        "{%0,%1,%2,%3}, {%4,%5,%6,%7}, {%8,%9}, {%0,%1,%2,%3};"
                        : "+f"(acc[i][j][0]), "+f"(acc[i][j][1]),
                          "+f"(acc[i][j][2]), "+f"(acc[i][j][3])
                        : "r"(af[i][0]), "r"(af[i][1]), "r"(af[i][2]), "r"(af[i][3]),
                          "r"(bb0), "r"(bb1));
                }
        }
    }

    // Epilogue
    #pragma unroll
    for (int i = 0; i < 4; i++) {
        int r0 = brow + warp_m + i * 16 + g;
        #pragma unroll
        for (int j = 0; j < 4; j++) {
            int c = bcol + warp_n + j * 8 + tg * 2;
            float e0 = acc[i][j][0], e1 = acc[i][j][1];
            float e2 = acc[i][j][2], e3 = acc[i][j][3];
            if (ID == 0) {
                __half2 lo = __floats2half2_rn(silu_f(e0), silu_f(e1));
                __half2 hi = __floats2half2_rn(silu_f(e2), silu_f(e3));
                *(__half2*)&g_xp[(size_t)r0 * N + c]       = lo;
                *(__half2*)&g_xp[(size_t)(r0 + 8) * N + c] = hi;
            } else if (ID == 1) {
                float b0 = bias[c], b1 = bias[c + 1];
                *(float2*)&g_wx[(size_t)r0 * N + c]       = make_float2(e0 + b0, e1 + b1);
                *(float2*)&g_wx[(size_t)(r0 + 8) * N + c] = make_float2(e2 + b0, e3 + b1);
            } else {
                *(float2*)&Cout[(size_t)r0 * N + c]       = make_float2(e0, e1);
                *(float2*)&Cout[(size_t)(r0 + 8) * N + c] = make_float2(e2, e3);
            }
        }
    }
}

// ---------------------------------------------------------------------------
// Sequential scan: 256 threads x 4 channels, 1 block/batch.
// 8-step register prefetch queue; shfl-tree warp reduction; one barrier/step;
// silu via __fdividef (fast rcp path). Gate stored as fp16.
// ---------------------------------------------------------------------------
__global__ __launch_bounds__(256)
void scan_kernel(const float* __restrict__ h0,
                 const float* __restrict__ log_alpha,
                 float* __restrict__ h_final)
{
    const int b    = blockIdx.x;
    const int tid  = threadIdx.x;
    const int w    = tid >> 5;
    const int lane = tid & 31;
    __shared__ __align__(16) float wsum[2][8];

    const float alpha = expf(log_alpha[0]);

    float4 hv = *(const float4*)&h0[b * DI + tid * 4];
    float h[4] = {hv.x, hv.y, hv.z, hv.w};

    const size_t base = (size_t)b * TT * DI + tid * 4;
    float4 q[8];
    #pragma unroll
    for (int i = 0; i < 8; i++)
        q[i] = *(const float4*)&g_wx[base + (size_t)i * DI];

    for (int t0 = 0; t0 < TT; t0 += 8) {
        #pragma unroll
        for (int u = 0; u < 8; u++) {
            const int t = t0 + u;

            float4 nx = make_float4(0.f, 0.f, 0.f, 0.f);
            if (t + 8 < TT)
                nx = *(const float4*)&g_wx[base + (size_t)(t + 8) * DI];

            const float4 cur = q[u];
            h[0] = fmaf(alpha, cur.x, h[0]);
            h[1] = fmaf(alpha, cur.y, h[1]);
            h[2] = fmaf(alpha, cur.z, h[2]);
            h[3] = fmaf(alpha, cur.w, h[3]);

            float s = fmaf(h[0], h[0], h[1] * h[1])
                    + fmaf(h[2], h[2], h[3] * h[3]);
            s = warp_sum(s);
            if (lane == 0) wsum[t & 1][w] = s;
            __syncthreads();

            float4 w0 = *(const float4*)&wsum[t & 1][0];
            float4 w1 = *(const float4*)&wsum[t & 1][4];
            float tot = ((w0.x + w0.y) + (w0.z + w0.w))
                      + ((w1.x + w1.y) + (w1.z + w1.w));
            float r = rsqrtf(tot * (1.0f / DI) + EPS);

            float o4[4];
            #pragma unroll
            for (int i = 0; i < 4; i++) {
                h[i] *= r;
                // h * silu(h) = h^2 / (1 + e^-h), fast-division path
                o4[i] = __fdividef(h[i] * h[i], 1.0f + __expf(-h[i]));
            }
            __half2 p01 = __floats2half2_rn(o4[0], o4[1]);
            __half2 p23 = __floats2half2_rn(o4[2], o4[3]);
            uint2 pk; pk.x = *(uint32_t*)&p01; pk.y = *(uint32_t*)&p23;
            *(uint2*)&g_gate[base + (size_t)t * DI] = pk;

            q[u] = nx;
        }
    }

    if (h_final)
        *(float4*)&h_final[b * DI + tid * 4] = make_float4(h[0], h[1], h[2], h[3]);
}

// ---------------------------------------------------------------------------
extern "C" void kernel_launch(void* const* d_in, const int* in_sizes, int n_in,
                              void* d_out, int out_size)
{
    const float* x         = (const float*)d_in[0];
    const float* h0        = (const float*)d_in[1];
    const float* W_in      = (const float*)d_in[2];
    const float* W_cell    = (const float*)d_in[3];
    const float* b_cell    = (const float*)d_in[4];
    const float* log_alpha = (const float*)d_in[5];
    const float* W_out     = (const float*)d_in[6];

    float* y = (float*)d_out;
    const size_t y_elems = (size_t)MM * DIM;
    float* h_final = ((size_t)out_size >= y_elems + (size_t)BAT * DI)
                         ? y + y_elems : nullptr;

    cudaFuncSetAttribute(gemm_hc<0>, cudaFuncAttributeMaxDynamicSharedMemorySize, SMEM_BYTES);
    cudaFuncSetAttribute(gemm_hc<1>, cudaFuncAttributeMaxDynamicSharedMemorySize, SMEM_BYTES);
    cudaFuncSetAttribute(gemm_hc<2>, cudaFuncAttributeMaxDynamicSharedMemorySize, SMEM_BYTES);

    __half *xa, *wi, *wc, *wo;
    cudaGetSymbolAddress((void**)&xa, g_xa);
    cudaGetSymbolAddress((void**)&wi, g_wi);
    cudaGetSymbolAddress((void**)&wc, g_wc);
    cudaGetSymbolAddress((void**)&wo, g_wo);

    // 0) convert mma operands to fp16
    {
        int n4x = (MM * DIM) / 4;
        to_half_kernel<<<(n4x + 255) / 256, 256>>>(x, xa, n4x);
        int n4w = (DI * DIM) / 4;
        to_half_kernel<<<(n4w + 255) / 256, 256>>>(W_in,   wi, n4w);
        to_half_kernel<<<(n4w + 255) / 256, 256>>>(W_cell, wc, n4w);
        to_half_kernel<<<(n4w + 255) / 256, 256>>>(W_out,  wo, n4w);
    }

    dim3 block(256);
    dim3 grid(DI / 128, MM / 128);

    // 1) xp = silu(x @ W_in^T)          -> g_xp (fp16)
    gemm_hc<0><<<grid, block, SMEM_BYTES>>>(nullptr, nullptr);
    // 2) Wx = xp @ W_cell^T + b_cell    -> g_wx (fp32)
    gemm_hc<1><<<grid, block, SMEM_BYTES>>>(b_cell, nullptr);
    // 3) scan                            -> g_gate (fp16), h_final
    scan_kernel<<<BAT, 256>>>(h0, log_alpha, h_final);
    // 4) y = gate @ W_out^T             -> d_out
    gemm_hc<2><<<dim3(DIM / 128, MM / 128), block, SMEM_BYTES>>>(nullptr, y);
}